// round 1
// baseline (speedup 1.0000x reference)
#include <cuda_runtime.h>
#include <cuda_bf16.h>

// Problem dims (fixed by setup_inputs)
#define BB 128   // batch
#define TT 512   // time
#define DD 256   // input dim
#define HH 512   // hidden dim
#define BH (BB*HH)        // 65536
#define TBH (TT*BH)       // 33554432 per projection

// Scratch for the three projections, layout [T][B][H] each.
// (Static __device__ array: allocation-free per harness rules.)
__device__ float g_scratch[3u * TBH];

// ---------------------------------------------------------------------------
// Phase 1: fused 3-way GEMM.
//   pr/pz/ph[t,b,h] = sum_d x[b,t,d] * W{r,z,h}[d,h]
// A = x viewed as [M=B*T, K=256] (m = b*512 + t, row-major, contiguous).
// Tiles: BM=64, BN=64, BK=16; 256 threads; 4x4 micro-tile per weight.
// ---------------------------------------------------------------------------
#define BM 64
#define BN 64
#define BK 16

__global__ __launch_bounds__(256)
void proj_gemm(const float* __restrict__ x,
               const float* __restrict__ wr,
               const float* __restrict__ wz,
               const float* __restrict__ wh)
{
    __shared__ __align__(16) float As[BK][BM + 4];      // [k][m], padded
    __shared__ __align__(16) float Bs[3][BK][BN];       // [w][k][n]

    const int tid = threadIdx.x;
    const int m0  = blockIdx.y * BM;
    const int n0  = blockIdx.x * BN;
    const int tx  = tid & 15;        // n sub-tile (16 x 4 cols)
    const int ty  = tid >> 4;        // m sub-tile (16 x 4 rows)

    const float* ws0 = wr;
    const float* ws1 = wz;
    const float* ws2 = wh;

    float acc[3][4][4];
#pragma unroll
    for (int w = 0; w < 3; w++)
#pragma unroll
        for (int i = 0; i < 4; i++)
#pragma unroll
            for (int j = 0; j < 4; j++)
                acc[w][i][j] = 0.0f;

    // A-load mapping: row = tid>>2 (64 rows), 4 cols at (tid&3)*4
    const int a_row = tid >> 2;
    const int a_c4  = (tid & 3) * 4;
    // B-load mapping: row = tid>>4 (16 rows), 4 cols at (tid&15)*4
    const int b_row = tid >> 4;
    const int b_c4  = (tid & 15) * 4;

    for (int k0 = 0; k0 < DD; k0 += BK) {
        // Load A tile (transposed into As[k][m])
        {
            float4 v = *(const float4*)(x + (size_t)(m0 + a_row) * DD + k0 + a_c4);
            As[a_c4 + 0][a_row] = v.x;
            As[a_c4 + 1][a_row] = v.y;
            As[a_c4 + 2][a_row] = v.z;
            As[a_c4 + 3][a_row] = v.w;
        }
        // Load the three B tiles
        {
            const size_t off = (size_t)(k0 + b_row) * HH + n0 + b_c4;
            *(float4*)&Bs[0][b_row][b_c4] = *(const float4*)(ws0 + off);
            *(float4*)&Bs[1][b_row][b_c4] = *(const float4*)(ws1 + off);
            *(float4*)&Bs[2][b_row][b_c4] = *(const float4*)(ws2 + off);
        }
        __syncthreads();

#pragma unroll
        for (int k = 0; k < BK; k++) {
            float4 a  = *(const float4*)&As[k][ty * 4];
            float4 b0 = *(const float4*)&Bs[0][k][tx * 4];
            float4 b1 = *(const float4*)&Bs[1][k][tx * 4];
            float4 b2 = *(const float4*)&Bs[2][k][tx * 4];
            float av[4] = {a.x, a.y, a.z, a.w};
            float bv0[4] = {b0.x, b0.y, b0.z, b0.w};
            float bv1[4] = {b1.x, b1.y, b1.z, b1.w};
            float bv2[4] = {b2.x, b2.y, b2.z, b2.w};
#pragma unroll
            for (int i = 0; i < 4; i++) {
#pragma unroll
                for (int j = 0; j < 4; j++) {
                    acc[0][i][j] = fmaf(av[i], bv0[j], acc[0][i][j]);
                    acc[1][i][j] = fmaf(av[i], bv1[j], acc[1][i][j]);
                    acc[2][i][j] = fmaf(av[i], bv2[j], acc[2][i][j]);
                }
            }
        }
        __syncthreads();
    }

    // Epilogue: write to scratch in [T][B][H] layout.
    // m = b*512 + t  ->  b = m>>9, t = m&511
#pragma unroll
    for (int w = 0; w < 3; w++) {
#pragma unroll
        for (int i = 0; i < 4; i++) {
            int m = m0 + ty * 4 + i;
            int bb = m >> 9;
            int t  = m & 511;
            float* dst = g_scratch + (size_t)w * TBH + (size_t)t * BH + bb * HH + n0 + tx * 4;
            float4 v = make_float4(acc[w][i][0], acc[w][i][1], acc[w][i][2], acc[w][i][3]);
            *(float4*)dst = v;
        }
    }
}

// ---------------------------------------------------------------------------
// Phase 2: diagonal recurrence scan. One thread per (b, h) lane.
// ---------------------------------------------------------------------------
__global__ __launch_bounds__(256)
void scan_kernel(const float* __restrict__ h0,
                 const float* __restrict__ mr,
                 const float* __restrict__ mz,
                 const float* __restrict__ br,
                 const float* __restrict__ bz,
                 float* __restrict__ out)
{
    const int idx = blockIdx.x * blockDim.x + threadIdx.x;   // 0..65535
    const int h = idx & (HH - 1);
    const int b = idx >> 9;   // HH = 512

    float state = h0[idx];
    const float mrv = mr[h];
    const float mzv = mz[h];
    const float brv = br[h];
    const float bzv = bz[h];

    const float* pr = g_scratch;
    const float* pz = g_scratch + TBH;
    const float* ph = g_scratch + 2u * TBH;

    float* o = out + (size_t)b * (TT * HH) + h;

#pragma unroll 4
    for (int t = 0; t < TT; t++) {
        const size_t off = (size_t)t * BH + idx;
        float a = __ldg(pr + off);
        float c = __ldg(pz + off);
        float d = __ldg(ph + off);

        float r = tanhf(a + brv + state * mrv) + 1.0f;
        float zex = __expf(-(c + bzv + state * mzv));
        float z = 1.0f / (1.0f + zex);
        state = z * state + (1.0f - z) * tanhf(d + r * state);

        o[(size_t)t * HH] = state;
    }
}

// ---------------------------------------------------------------------------
// Launch
// ---------------------------------------------------------------------------
extern "C" void kernel_launch(void* const* d_in, const int* in_sizes, int n_in,
                              void* d_out, int out_size)
{
    const float* x  = (const float*)d_in[0];
    const float* h0 = (const float*)d_in[1];
    const float* wr = (const float*)d_in[2];
    const float* wz = (const float*)d_in[3];
    const float* wh = (const float*)d_in[4];
    const float* mr = (const float*)d_in[5];
    const float* mz = (const float*)d_in[6];
    const float* br = (const float*)d_in[7];
    const float* bz = (const float*)d_in[8];
    float* out = (float*)d_out;

    dim3 ggrid(HH / BN, (BB * TT) / BM);   // (8, 1024)
    proj_gemm<<<ggrid, 256>>>(x, wr, wz, wh);

    scan_kernel<<<BH / 256, 256>>>(h0, mr, mz, br, bz, out);
}

// round 3
// speedup vs baseline: 1.7928x; 1.7928x over previous
#include <cuda_runtime.h>
#include <cuda_bf16.h>
#include <cstdint>

// Problem dims (fixed by setup_inputs)
#define BB 128
#define TT 512
#define DD 256
#define HH 512
#define BH (BB*HH)        // 65536
#define TBH (TT*BH)       // 33554432 per projection
#define MM (BB*TT)        // 65536 GEMM rows

// ---------------------------------------------------------------------------
// Static device scratch (allocation-free per harness rules)
// ---------------------------------------------------------------------------
__device__ float g_scratch[3u * TBH];                       // 402 MB projections [w][T][B][H]
__device__ __nv_bfloat16 g_asplit[(size_t)MM * 512];        // 64 MB: [m][k], k<256 = x_hi, k>=256 = x_lo
__device__ __nv_bfloat16 g_bsplit[3u * 512 * 512];          // 1.5 MB: [w][n][k], k<256 = w_hi, k>=256 = w_lo

__device__ __forceinline__ uint32_t smem_u32(const void* p) {
    uint32_t a;
    asm("{ .reg .u64 t; cvta.to.shared.u64 t, %1; cvt.u32.u64 %0, t; }" : "=r"(a) : "l"(p));
    return a;
}

#define CP_ASYNC_16(smem, gmem) \
    asm volatile("cp.async.cg.shared.global [%0], [%1], 16;" :: "r"(smem), "l"(gmem))
#define CP_ASYNC_COMMIT() asm volatile("cp.async.commit_group;")
#define CP_ASYNC_WAIT_ALL() asm volatile("cp.async.wait_group 0;")

// ---------------------------------------------------------------------------
// Kernel 0a: split x -> (hi, lo) bf16  (A' = [M, 512])
// ---------------------------------------------------------------------------
__global__ __launch_bounds__(256)
void convert_x(const float* __restrict__ x)
{
    int i = blockIdx.x * blockDim.x + threadIdx.x;     // float4 index, total MM*256/4
    float4 v = ((const float4*)x)[i];
    int m = i >> 6;
    int k = (i & 63) * 4;
    float vv[4] = {v.x, v.y, v.z, v.w};
    union { __nv_bfloat16 b[4]; uint2 u; } H, L;
#pragma unroll
    for (int j = 0; j < 4; j++) {
        H.b[j] = __float2bfloat16(vv[j]);
        L.b[j] = __float2bfloat16(vv[j] - __bfloat162float(H.b[j]));
    }
    *(uint2*)(g_asplit + (size_t)m * 512 + k)       = H.u;
    *(uint2*)(g_asplit + (size_t)m * 512 + 256 + k) = L.u;
}

// ---------------------------------------------------------------------------
// Kernel 0b: split + transpose weights -> B' = [w][n=h][k=d] (hi, lo)
// ---------------------------------------------------------------------------
__global__ __launch_bounds__(256)
void convert_w(const float* __restrict__ wr, const float* __restrict__ wz, const float* __restrict__ wh)
{
    int i = blockIdx.x * blockDim.x + threadIdx.x;     // total 3*256*512
    int w = i / (DD * HH);
    int rem = i - w * (DD * HH);
    int d = rem >> 9;
    int h = rem & 511;
    const float* W = (w == 0) ? wr : ((w == 1) ? wz : wh);
    float v = W[d * HH + h];
    __nv_bfloat16 hi = __float2bfloat16(v);
    __nv_bfloat16 lo = __float2bfloat16(v - __bfloat162float(hi));
    size_t base = ((size_t)w * 512 + h) * 512;
    g_bsplit[base + d]       = hi;
    g_bsplit[base + 256 + d] = lo;
}

// ---------------------------------------------------------------------------
// Kernel 1: mma.sync bf16 GEMM (portable ISA, works on plain sm_100).
// Block tile 128(M) x 128(N), K-tile 32, logical K = 768 (hi*hi + lo*hi + hi*lo).
// 8 warps: 2 (m) x 4 (n); warp tile 64x32 via m16n8k16.
// cp.async double-buffered smem, padded pitch 40 bf16 (conflict-free ldmatrix).
// grid = (12 n-tiles[w,nbase], 512 m-tiles), 256 threads.
// ---------------------------------------------------------------------------
#define PITCH 40

__global__ __launch_bounds__(256)
void gemm_mma()
{
    __shared__ __align__(16) __nv_bfloat16 As[2][128][PITCH];
    __shared__ __align__(16) __nv_bfloat16 Bs[2][128][PITCH];

    const int tid  = threadIdx.x;
    const int wid  = tid >> 5;
    const int lane = tid & 31;
    const int warp_m = wid >> 2;       // 0..1
    const int warp_n = wid & 3;        // 0..3

    const int nt    = blockIdx.x;      // 0..11
    const int m0    = blockIdx.y * 128;
    const int w_idx = nt >> 2;
    const int nbase = (nt & 3) * 128;
    const __nv_bfloat16* gB = g_bsplit + ((size_t)w_idx * 512 + nbase) * 512;

    // cp.async mapping: 512 16B-transfers per tile, 2 per thread
    const int ld_row0 = tid >> 1;            // rows 0..127
    const int ld_c0   = (tid & 1) * 16;      // col offset in bf16 (two 16B chunks per half-row pair)
    // Each thread does rows tid>>1 cols [c0, c0+8) and [c0+... ] -> simpler: idx scheme
    // idx = tid, tid+256 ; row = idx>>2, c16 = idx&3 (16B chunk -> 8 bf16)
    (void)ld_row0; (void)ld_c0;

    float acc[4][4][4];
#pragma unroll
    for (int i = 0; i < 4; i++)
#pragma unroll
        for (int j = 0; j < 4; j++)
#pragma unroll
            for (int q = 0; q < 4; q++) acc[i][j][q] = 0.0f;

    auto load_chunk = [&](int stage, int ak, int bk) {
#pragma unroll
        for (int it = 0; it < 2; it++) {
            int idx = tid + it * 256;
            int r = idx >> 2, c = (idx & 3) * 8;
            uint32_t sa = smem_u32(&As[stage][r][c]);
            CP_ASYNC_16(sa, g_asplit + (size_t)(m0 + r) * 512 + ak + c);
            uint32_t sb = smem_u32(&Bs[stage][r][c]);
            CP_ASYNC_16(sb, gB + (size_t)r * 512 + bk + c);
        }
        CP_ASYNC_COMMIT();
    };

    // chunk -> (ak, bk): pass0 hi*hi, pass1 lo*hi, pass2 hi*lo
    auto chunk_off = [&](int c, int& ak, int& bk) {
        int p = c >> 3;
        int q = (c & 7) * 32;
        ak = (p == 1) ? 256 + q : q;
        bk = (p == 2) ? 256 + q : q;
    };

    {
        int ak, bk; chunk_off(0, ak, bk);
        load_chunk(0, ak, bk);
    }

    // ldmatrix per-lane source addresses (row/col within the tile)
    const int a_row_sel = warp_m * 64 + (lane & 15);         // + mi*16
    const int a_col_sel = (lane & 16) ? 8 : 0;               // + kk*16
    const int b_row_sel = warp_n * 32 + (lane & 7);          // + ni*8
    const int b_col_sel = (lane & 8) ? 8 : 0;                // + kk*16

    for (int c = 0; c < 24; c++) {
        const int st = c & 1;
        CP_ASYNC_WAIT_ALL();
        __syncthreads();
        if (c + 1 < 24) {
            int ak, bk; chunk_off(c + 1, ak, bk);
            load_chunk(st ^ 1, ak, bk);
        }

#pragma unroll
        for (int kk = 0; kk < 2; kk++) {
            uint32_t afrag[4][4];
            uint32_t bfrag[4][2];
#pragma unroll
            for (int mi = 0; mi < 4; mi++) {
                uint32_t addr = smem_u32(&As[st][a_row_sel + mi * 16][kk * 16 + a_col_sel]);
                asm volatile("ldmatrix.sync.aligned.m8n8.x4.shared.b16 {%0,%1,%2,%3}, [%4];"
                    : "=r"(afrag[mi][0]), "=r"(afrag[mi][1]), "=r"(afrag[mi][2]), "=r"(afrag[mi][3])
                    : "r"(addr));
            }
#pragma unroll
            for (int ni = 0; ni < 4; ni++) {
                uint32_t addr = smem_u32(&Bs[st][b_row_sel + ni * 8][kk * 16 + b_col_sel]);
                asm volatile("ldmatrix.sync.aligned.m8n8.x2.shared.b16 {%0,%1}, [%2];"
                    : "=r"(bfrag[ni][0]), "=r"(bfrag[ni][1])
                    : "r"(addr));
            }
#pragma unroll
            for (int mi = 0; mi < 4; mi++) {
#pragma unroll
                for (int ni = 0; ni < 4; ni++) {
                    asm volatile(
                        "mma.sync.aligned.m16n8k16.row.col.f32.bf16.bf16.f32 "
                        "{%0,%1,%2,%3}, {%4,%5,%6,%7}, {%8,%9}, {%0,%1,%2,%3};"
                        : "+f"(acc[mi][ni][0]), "+f"(acc[mi][ni][1]),
                          "+f"(acc[mi][ni][2]), "+f"(acc[mi][ni][3])
                        : "r"(afrag[mi][0]), "r"(afrag[mi][1]), "r"(afrag[mi][2]), "r"(afrag[mi][3]),
                          "r"(bfrag[ni][0]), "r"(bfrag[ni][1]));
                }
            }
        }
        __syncthreads();
    }

    // Epilogue: scatter C (128x128 fp32) to g_scratch [w][t][b][h]
    const int g  = lane >> 2;        // groupID 0..7
    const int tg = lane & 3;         // 0..3
#pragma unroll
    for (int mi = 0; mi < 4; mi++) {
#pragma unroll
        for (int rr = 0; rr < 2; rr++) {
            int m = m0 + warp_m * 64 + mi * 16 + g + rr * 8;
            int bb = m >> 9;
            int t  = m & 511;
            float* dst = g_scratch + (size_t)w_idx * TBH + (size_t)t * BH + (size_t)bb * HH
                       + nbase + warp_n * 32 + tg * 2;
#pragma unroll
            for (int ni = 0; ni < 4; ni++) {
                float2 v = rr ? make_float2(acc[mi][ni][2], acc[mi][ni][3])
                              : make_float2(acc[mi][ni][0], acc[mi][ni][1]);
                *(float2*)(dst + ni * 8) = v;
            }
        }
    }
}

// ---------------------------------------------------------------------------
// Kernel 2: diagonal recurrence scan, software-pipelined loads.
// ---------------------------------------------------------------------------
__global__ __launch_bounds__(256)
void scan_kernel(const float* __restrict__ h0,
                 const float* __restrict__ mr,
                 const float* __restrict__ mz,
                 const float* __restrict__ br,
                 const float* __restrict__ bz,
                 float* __restrict__ out)
{
    const int idx = blockIdx.x * blockDim.x + threadIdx.x;   // 0..65535
    const int h = idx & (HH - 1);
    const int b = idx >> 9;

    float state = h0[idx];
    const float mrv = mr[h];
    const float mzv = mz[h];
    const float brv = br[h];
    const float bzv = bz[h];

    const float* pr = g_scratch;
    const float* pz = g_scratch + TBH;
    const float* ph = g_scratch + 2u * TBH;

    float* o = out + (size_t)b * (TT * HH) + h;

    size_t off = (size_t)idx;
    float a0 = __ldg(pr + off);
    float c0 = __ldg(pz + off);
    float d0 = __ldg(ph + off);

#pragma unroll 4
    for (int t = 0; t < TT; t++) {
        float a1 = 0.f, c1 = 0.f, d1 = 0.f;
        if (t + 1 < TT) {
            size_t noff = off + BH;
            a1 = __ldg(pr + noff);
            c1 = __ldg(pz + noff);
            d1 = __ldg(ph + noff);
        }

        float r = tanhf(a0 + brv + state * mrv) + 1.0f;
        float zex = __expf(-(c0 + bzv + state * mzv));
        float z = 1.0f / (1.0f + zex);
        state = z * state + (1.0f - z) * tanhf(d0 + r * state);

        o[(size_t)t * HH] = state;

        a0 = a1; c0 = c1; d0 = d1;
        off += BH;
    }
}

// ---------------------------------------------------------------------------
// Launch
// ---------------------------------------------------------------------------
extern "C" void kernel_launch(void* const* d_in, const int* in_sizes, int n_in,
                              void* d_out, int out_size)
{
    const float* x  = (const float*)d_in[0];
    const float* h0 = (const float*)d_in[1];
    const float* wr = (const float*)d_in[2];
    const float* wz = (const float*)d_in[3];
    const float* wh = (const float*)d_in[4];
    const float* mr = (const float*)d_in[5];
    const float* mz = (const float*)d_in[6];
    const float* br = (const float*)d_in[7];
    const float* bz = (const float*)d_in[8];
    float* out = (float*)d_out;

    convert_x<<<(MM * DD / 4) / 256, 256>>>(x);
    convert_w<<<(3 * DD * HH) / 256, 256>>>(wr, wz, wh);

    dim3 ggrid(12, MM / 128);   // (12, 512)
    gemm_mma<<<ggrid, 256>>>();

    scan_kernel<<<BH / 256, 256>>>(h0, mr, mz, br, bz, out);
}

// round 4
// speedup vs baseline: 2.1367x; 1.1918x over previous
#include <cuda_runtime.h>
#include <cuda_bf16.h>
#include <cstdint>

// Problem dims (fixed by setup_inputs)
#define BB 128
#define TT 512
#define DD 256
#define HH 512
#define BH (BB*HH)        // 65536
#define TBH (TT*BH)       // 33554432 per projection
#define MM (BB*TT)        // 65536 GEMM rows

// ---------------------------------------------------------------------------
// Static device scratch (allocation-free per harness rules)
// ---------------------------------------------------------------------------
__device__ float g_scratch[3u * TBH];                       // 402 MB projections [w][T][B][H]
__device__ __nv_bfloat16 g_asplit[(size_t)MM * 512];        // 64 MB: [m][k], k<256 = x_hi, k>=256 = x_lo
__device__ __nv_bfloat16 g_bsplit[3u * 512 * 512];          // 1.5 MB: [w][n][k], k<256 = w_hi, k>=256 = w_lo

__device__ __forceinline__ uint32_t smem_u32(const void* p) {
    uint32_t a;
    asm("{ .reg .u64 t; cvta.to.shared.u64 t, %1; cvt.u32.u64 %0, t; }" : "=r"(a) : "l"(p));
    return a;
}

#define CP_ASYNC_16(smem, gmem) \
    asm volatile("cp.async.cg.shared.global [%0], [%1], 16;" :: "r"(smem), "l"(gmem))
#define CP_ASYNC_COMMIT() asm volatile("cp.async.commit_group;")
#define CP_ASYNC_WAIT_2() asm volatile("cp.async.wait_group 2;")

// ---------------------------------------------------------------------------
// Kernel 0a: split x -> (hi, lo) bf16  (A' = [M, 512])
// ---------------------------------------------------------------------------
__global__ __launch_bounds__(256)
void convert_x(const float* __restrict__ x)
{
    int i = blockIdx.x * blockDim.x + threadIdx.x;     // float4 index, total MM*256/4
    float4 v = ((const float4*)x)[i];
    int m = i >> 6;
    int k = (i & 63) * 4;
    float vv[4] = {v.x, v.y, v.z, v.w};
    union { __nv_bfloat16 b[4]; uint2 u; } H, L;
#pragma unroll
    for (int j = 0; j < 4; j++) {
        H.b[j] = __float2bfloat16(vv[j]);
        L.b[j] = __float2bfloat16(vv[j] - __bfloat162float(H.b[j]));
    }
    *(uint2*)(g_asplit + (size_t)m * 512 + k)       = H.u;
    *(uint2*)(g_asplit + (size_t)m * 512 + 256 + k) = L.u;
}

// ---------------------------------------------------------------------------
// Kernel 0b: split + transpose weights -> B' = [w][n=h][k=d] (hi, lo)
// ---------------------------------------------------------------------------
__global__ __launch_bounds__(256)
void convert_w(const float* __restrict__ wr, const float* __restrict__ wz, const float* __restrict__ wh)
{
    int i = blockIdx.x * blockDim.x + threadIdx.x;     // total 3*256*512
    int w = i / (DD * HH);
    int rem = i - w * (DD * HH);
    int d = rem >> 9;
    int h = rem & 511;
    const float* W = (w == 0) ? wr : ((w == 1) ? wz : wh);
    float v = W[d * HH + h];
    __nv_bfloat16 hi = __float2bfloat16(v);
    __nv_bfloat16 lo = __float2bfloat16(v - __bfloat162float(hi));
    size_t base = ((size_t)w * 512 + h) * 512;
    g_bsplit[base + d]       = hi;
    g_bsplit[base + 256 + d] = lo;
}

// ---------------------------------------------------------------------------
// Kernel 1: mma.sync bf16 GEMM, 4-stage cp.async pipeline.
// Block tile 128(M) x 128(N), K-chunk 32, logical K = 768 (hi*hi + lo*hi + hi*lo).
// 8 warps: 2 (m) x 4 (n); warp tile 64x32 via m16n8k16.
// Dynamic smem: 4 stages x (As 128x40 + Bs 128x40) bf16 = 80 KB, 2 CTAs/SM.
// grid = (12 n-tiles[w,nbase], 512 m-tiles), 256 threads.
// ---------------------------------------------------------------------------
#define PITCH 40
#define NSTAGE 4
#define TILE_ELT (128 * PITCH)                     // bf16 per tile per stage
#define STAGE_ELT (2 * TILE_ELT)                   // A + B
#define GEMM_SMEM (NSTAGE * STAGE_ELT * 2)         // bytes = 81920

__global__ __launch_bounds__(256, 2)
void gemm_mma()
{
    extern __shared__ __align__(16) __nv_bfloat16 sm[];

    const int tid  = threadIdx.x;
    const int wid  = tid >> 5;
    const int lane = tid & 31;
    const int warp_m = wid >> 2;       // 0..1
    const int warp_n = wid & 3;        // 0..3

    const int nt    = blockIdx.x;      // 0..11
    const int m0    = blockIdx.y * 128;
    const int w_idx = nt >> 2;
    const int nbase = (nt & 3) * 128;
    const __nv_bfloat16* gB = g_bsplit + ((size_t)w_idx * 512 + nbase) * 512;

    float acc[4][4][4];
#pragma unroll
    for (int i = 0; i < 4; i++)
#pragma unroll
        for (int j = 0; j < 4; j++)
#pragma unroll
            for (int q = 0; q < 4; q++) acc[i][j][q] = 0.0f;

    // chunk -> (ak, bk): pass0 hi*hi, pass1 lo*hi, pass2 hi*lo
    auto chunk_off = [&](int c, int& ak, int& bk) {
        int p = c >> 3;
        int q = (c & 7) * 32;
        ak = (p == 1) ? 256 + q : q;
        bk = (p == 2) ? 256 + q : q;
    };

    // Per-thread load mapping (2 x 16B per tile): idx = tid + it*256;
    // row = idx>>2, col = (idx&3)*8
    auto load_chunk = [&](int stage, int c) {
        if (c < 24) {
            int ak, bk; chunk_off(c, ak, bk);
            __nv_bfloat16* As = sm + stage * STAGE_ELT;
            __nv_bfloat16* Bs = As + TILE_ELT;
#pragma unroll
            for (int it = 0; it < 2; it++) {
                int idx = tid + it * 256;
                int r = idx >> 2, cc = (idx & 3) * 8;
                CP_ASYNC_16(smem_u32(As + r * PITCH + cc),
                            g_asplit + (size_t)(m0 + r) * 512 + ak + cc);
                CP_ASYNC_16(smem_u32(Bs + r * PITCH + cc),
                            gB + (size_t)r * 512 + bk + cc);
            }
        }
        CP_ASYNC_COMMIT();   // always commit (possibly-empty group keeps counts uniform)
    };

    // Prologue: stages 0,1,2 <- chunks 0,1,2
    load_chunk(0, 0);
    load_chunk(1, 1);
    load_chunk(2, 2);

    // ldmatrix per-lane selectors
    const int a_row_sel = warp_m * 64 + (lane & 15);
    const int a_col_sel = (lane & 16) ? 8 : 0;
    const int b_row_sel = warp_n * 32 + (lane & 7);
    const int b_col_sel = (lane & 8) ? 8 : 0;

    for (int c = 0; c < 24; c++) {
        const int st = c & (NSTAGE - 1);
        CP_ASYNC_WAIT_2();          // chunk c resident
        __syncthreads();            // also guarantees stage (c-1)%4 fully consumed
        load_chunk((c + 3) & (NSTAGE - 1), c + 3);

        const __nv_bfloat16* As = sm + st * STAGE_ELT;
        const __nv_bfloat16* Bs = As + TILE_ELT;

#pragma unroll
        for (int kk = 0; kk < 2; kk++) {
            uint32_t afrag[4][4];
            uint32_t bfrag[4][2];
#pragma unroll
            for (int mi = 0; mi < 4; mi++) {
                uint32_t addr = smem_u32(As + (a_row_sel + mi * 16) * PITCH + kk * 16 + a_col_sel);
                asm volatile("ldmatrix.sync.aligned.m8n8.x4.shared.b16 {%0,%1,%2,%3}, [%4];"
                    : "=r"(afrag[mi][0]), "=r"(afrag[mi][1]), "=r"(afrag[mi][2]), "=r"(afrag[mi][3])
                    : "r"(addr));
            }
#pragma unroll
            for (int ni = 0; ni < 4; ni++) {
                uint32_t addr = smem_u32(Bs + (b_row_sel + ni * 8) * PITCH + kk * 16 + b_col_sel);
                asm volatile("ldmatrix.sync.aligned.m8n8.x2.shared.b16 {%0,%1}, [%2];"
                    : "=r"(bfrag[ni][0]), "=r"(bfrag[ni][1])
                    : "r"(addr));
            }
#pragma unroll
            for (int mi = 0; mi < 4; mi++) {
#pragma unroll
                for (int ni = 0; ni < 4; ni++) {
                    asm volatile(
                        "mma.sync.aligned.m16n8k16.row.col.f32.bf16.bf16.f32 "
                        "{%0,%1,%2,%3}, {%4,%5,%6,%7}, {%8,%9}, {%0,%1,%2,%3};"
                        : "+f"(acc[mi][ni][0]), "+f"(acc[mi][ni][1]),
                          "+f"(acc[mi][ni][2]), "+f"(acc[mi][ni][3])
                        : "r"(afrag[mi][0]), "r"(afrag[mi][1]), "r"(afrag[mi][2]), "r"(afrag[mi][3]),
                          "r"(bfrag[ni][0]), "r"(bfrag[ni][1]));
                }
            }
        }
    }

    // Epilogue: scatter C (128x128 fp32) to g_scratch [w][t][b][h]
    const int g  = lane >> 2;
    const int tg = lane & 3;
#pragma unroll
    for (int mi = 0; mi < 4; mi++) {
#pragma unroll
        for (int rr = 0; rr < 2; rr++) {
            int m = m0 + warp_m * 64 + mi * 16 + g + rr * 8;
            int bb = m >> 9;
            int t  = m & 511;
            float* dst = g_scratch + (size_t)w_idx * TBH + (size_t)t * BH + (size_t)bb * HH
                       + nbase + warp_n * 32 + tg * 2;
#pragma unroll
            for (int ni = 0; ni < 4; ni++) {
                float2 v = rr ? make_float2(acc[mi][ni][2], acc[mi][ni][3])
                              : make_float2(acc[mi][ni][0], acc[mi][ni][1]);
                *(float2*)(dst + ni * 8) = v;
            }
        }
    }
}

// ---------------------------------------------------------------------------
// Kernel 2: diagonal recurrence scan, depth-8 register ring prefetch.
// ---------------------------------------------------------------------------
__global__ __launch_bounds__(256)
void scan_kernel(const float* __restrict__ h0,
                 const float* __restrict__ mr,
                 const float* __restrict__ mz,
                 const float* __restrict__ br,
                 const float* __restrict__ bz,
                 float* __restrict__ out)
{
    const int idx = blockIdx.x * blockDim.x + threadIdx.x;   // 0..65535
    const int h = idx & (HH - 1);
    const int b = idx >> 9;

    float state = h0[idx];
    const float mrv = mr[h];
    const float mzv = mz[h];
    const float brv = br[h];
    const float bzv = bz[h];

    const float* pr = g_scratch + idx;
    const float* pz = g_scratch + TBH + idx;
    const float* ph = g_scratch + 2u * TBH + idx;

    float* o = out + (size_t)b * (TT * HH) + h;

    float pa[8], pc[8], pd[8];
#pragma unroll
    for (int u = 0; u < 8; u++) {
        size_t off = (size_t)u * BH;
        pa[u] = __ldg(pr + off);
        pc[u] = __ldg(pz + off);
        pd[u] = __ldg(ph + off);
    }

    for (int tb = 0; tb < TT; tb += 8) {
#pragma unroll
        for (int u = 0; u < 8; u++) {
            const int t = tb + u;
            float a0 = pa[u], c0 = pc[u], d0 = pd[u];

            // Refill ring slot for t+8 BEFORE the dependent compute chain
            if (t + 8 < TT) {
                size_t off = (size_t)(t + 8) * BH;
                pa[u] = __ldg(pr + off);
                pc[u] = __ldg(pz + off);
                pd[u] = __ldg(ph + off);
            }

            float r = tanhf(a0 + brv + state * mrv) + 1.0f;
            float zex = __expf(-(c0 + bzv + state * mzv));
            float z = 1.0f / (1.0f + zex);
            state = z * state + (1.0f - z) * tanhf(d0 + r * state);

            o[(size_t)t * HH] = state;
        }
    }
}

// ---------------------------------------------------------------------------
// Launch
// ---------------------------------------------------------------------------
extern "C" void kernel_launch(void* const* d_in, const int* in_sizes, int n_in,
                              void* d_out, int out_size)
{
    const float* x  = (const float*)d_in[0];
    const float* h0 = (const float*)d_in[1];
    const float* wr = (const float*)d_in[2];
    const float* wz = (const float*)d_in[3];
    const float* wh = (const float*)d_in[4];
    const float* mr = (const float*)d_in[5];
    const float* mz = (const float*)d_in[6];
    const float* br = (const float*)d_in[7];
    const float* bz = (const float*)d_in[8];
    float* out = (float*)d_out;

    static int smem_set = 0;
    if (!smem_set) {
        cudaFuncSetAttribute(gemm_mma, cudaFuncAttributeMaxDynamicSharedMemorySize, GEMM_SMEM);
        smem_set = 1;
    }

    convert_x<<<(MM * DD / 4) / 256, 256>>>(x);
    convert_w<<<(3 * DD * HH) / 256, 256>>>(wr, wz, wh);

    dim3 ggrid(12, MM / 128);   // (12, 512)
    gemm_mma<<<ggrid, 256, GEMM_SMEM>>>();

    scan_kernel<<<BH / 256, 256>>>(h0, mr, mz, br, bz, out);
}

// round 5
// speedup vs baseline: 2.6114x; 1.2222x over previous
#include <cuda_runtime.h>
#include <cuda_fp16.h>
#include <cstdint>

// Problem dims (fixed by setup_inputs)
#define BB 128
#define TT 512
#define DD 256
#define HH 512
#define BH (BB*HH)        // 65536
#define TBH (TT*BH)       // 33554432 per projection
#define MM (BB*TT)        // 65536 GEMM rows
#define TBH2 (TBH/2)
#define BH2 (BH/2)

// ---------------------------------------------------------------------------
// Static device scratch (allocation-free per harness rules)
// ---------------------------------------------------------------------------
__device__ __half g_scratch[3u * TBH];                 // 201 MB projections fp16 [w][T][B][H]
__device__ __half g_asplit[(size_t)MM * 512];          // 64 MB: [m][k], k<256 = x_hi, k>=256 = x_lo
__device__ __half g_bsplit[3u * 512 * 256];            // 0.75 MB: [w][n=h][k=d] fp16

__device__ __forceinline__ uint32_t smem_u32(const void* p) {
    uint32_t a;
    asm("{ .reg .u64 t; cvta.to.shared.u64 t, %1; cvt.u32.u64 %0, t; }" : "=r"(a) : "l"(p));
    return a;
}

#define CP_ASYNC_16(smem, gmem) \
    asm volatile("cp.async.cg.shared.global [%0], [%1], 16;" :: "r"(smem), "l"(gmem))
#define CP_ASYNC_COMMIT() asm volatile("cp.async.commit_group;")
#define CP_ASYNC_WAIT_2() asm volatile("cp.async.wait_group 2;")

// ---------------------------------------------------------------------------
// Kernel 0a: split x -> (hi, lo) fp16  (A' = [M, 512])
// ---------------------------------------------------------------------------
__global__ __launch_bounds__(256)
void convert_x(const float* __restrict__ x)
{
    int i = blockIdx.x * blockDim.x + threadIdx.x;     // float4 index, total MM*256/4
    float4 v = ((const float4*)x)[i];
    int m = i >> 6;
    int k = (i & 63) * 4;
    float vv[4] = {v.x, v.y, v.z, v.w};
    union { __half b[4]; uint2 u; } H, L;
#pragma unroll
    for (int j = 0; j < 4; j++) {
        H.b[j] = __float2half_rn(vv[j]);
        L.b[j] = __float2half_rn(vv[j] - __half2float(H.b[j]));
    }
    *(uint2*)(g_asplit + (size_t)m * 512 + k)       = H.u;
    *(uint2*)(g_asplit + (size_t)m * 512 + 256 + k) = L.u;
}

// ---------------------------------------------------------------------------
// Kernel 0b: fp16 + transpose weights -> B' = [w][n=h][k=d]
// ---------------------------------------------------------------------------
__global__ __launch_bounds__(256)
void convert_w(const float* __restrict__ wr, const float* __restrict__ wz, const float* __restrict__ wh)
{
    int i = blockIdx.x * blockDim.x + threadIdx.x;     // total 3*256*512
    int w = i / (DD * HH);
    int rem = i - w * (DD * HH);
    int d = rem >> 9;
    int h = rem & 511;
    const float* W = (w == 0) ? wr : ((w == 1) ? wz : wh);
    g_bsplit[((size_t)w * 512 + h) * 256 + d] = __float2half_rn(W[d * HH + h]);
}

// ---------------------------------------------------------------------------
// Kernel 1: mma.sync fp16 GEMM, 4-stage cp.async pipeline.
// Block tile 128(M) x 128(N), K-chunk 32, logical K = 512 (x_hi*w + x_lo*w).
// 8 warps: 2 (m) x 4 (n); warp tile 64x32 via m16n8k16.f32.f16.f16.f32.
// Dynamic smem: 4 stages x (As 128x40 + Bs 128x40) fp16 = 80 KB, 2 CTAs/SM.
// grid = (12 n-tiles[w,nbase], 512 m-tiles), 256 threads. 16 chunks.
// ---------------------------------------------------------------------------
#define PITCH 40
#define NSTAGE 4
#define TILE_ELT (128 * PITCH)
#define STAGE_ELT (2 * TILE_ELT)
#define GEMM_SMEM (NSTAGE * STAGE_ELT * 2)         // 81920 bytes
#define NCHUNK 16

__global__ __launch_bounds__(256, 2)
void gemm_mma()
{
    extern __shared__ __align__(16) __half sm[];

    const int tid  = threadIdx.x;
    const int wid  = tid >> 5;
    const int lane = tid & 31;
    const int warp_m = wid >> 2;       // 0..1
    const int warp_n = wid & 3;        // 0..3

    const int nt    = blockIdx.x;      // 0..11
    const int m0    = blockIdx.y * 128;
    const int w_idx = nt >> 2;
    const int nbase = (nt & 3) * 128;
    const __half* gB = g_bsplit + ((size_t)w_idx * 512 + nbase) * 256;

    float acc[4][4][4];
#pragma unroll
    for (int i = 0; i < 4; i++)
#pragma unroll
        for (int j = 0; j < 4; j++)
#pragma unroll
            for (int q = 0; q < 4; q++) acc[i][j][q] = 0.0f;

    // chunk -> (ak, bk): pass0 x_hi*w, pass1 x_lo*w
    auto chunk_off = [&](int c, int& ak, int& bk) {
        int q = (c & 7) * 32;
        ak = (c >= 8) ? 256 + q : q;
        bk = q;
    };

    auto load_chunk = [&](int stage, int c) {
        if (c < NCHUNK) {
            int ak, bk; chunk_off(c, ak, bk);
            __half* As = sm + stage * STAGE_ELT;
            __half* Bs = As + TILE_ELT;
#pragma unroll
            for (int it = 0; it < 2; it++) {
                int idx = tid + it * 256;
                int r = idx >> 2, cc = (idx & 3) * 8;
                CP_ASYNC_16(smem_u32(As + r * PITCH + cc),
                            g_asplit + (size_t)(m0 + r) * 512 + ak + cc);
                CP_ASYNC_16(smem_u32(Bs + r * PITCH + cc),
                            gB + (size_t)r * 256 + bk + cc);
            }
        }
        CP_ASYNC_COMMIT();
    };

    load_chunk(0, 0);
    load_chunk(1, 1);
    load_chunk(2, 2);

    const int a_row_sel = warp_m * 64 + (lane & 15);
    const int a_col_sel = (lane & 16) ? 8 : 0;
    const int b_row_sel = warp_n * 32 + (lane & 7);
    const int b_col_sel = (lane & 8) ? 8 : 0;

    for (int c = 0; c < NCHUNK; c++) {
        const int st = c & (NSTAGE - 1);
        CP_ASYNC_WAIT_2();
        __syncthreads();
        load_chunk((c + 3) & (NSTAGE - 1), c + 3);

        const __half* As = sm + st * STAGE_ELT;
        const __half* Bs = As + TILE_ELT;

#pragma unroll
        for (int kk = 0; kk < 2; kk++) {
            uint32_t afrag[4][4];
            uint32_t bfrag[4][2];
#pragma unroll
            for (int mi = 0; mi < 4; mi++) {
                uint32_t addr = smem_u32(As + (a_row_sel + mi * 16) * PITCH + kk * 16 + a_col_sel);
                asm volatile("ldmatrix.sync.aligned.m8n8.x4.shared.b16 {%0,%1,%2,%3}, [%4];"
                    : "=r"(afrag[mi][0]), "=r"(afrag[mi][1]), "=r"(afrag[mi][2]), "=r"(afrag[mi][3])
                    : "r"(addr));
            }
#pragma unroll
            for (int ni = 0; ni < 4; ni++) {
                uint32_t addr = smem_u32(Bs + (b_row_sel + ni * 8) * PITCH + kk * 16 + b_col_sel);
                asm volatile("ldmatrix.sync.aligned.m8n8.x2.shared.b16 {%0,%1}, [%2];"
                    : "=r"(bfrag[ni][0]), "=r"(bfrag[ni][1])
                    : "r"(addr));
            }
#pragma unroll
            for (int mi = 0; mi < 4; mi++) {
#pragma unroll
                for (int ni = 0; ni < 4; ni++) {
                    asm volatile(
                        "mma.sync.aligned.m16n8k16.row.col.f32.f16.f16.f32 "
                        "{%0,%1,%2,%3}, {%4,%5,%6,%7}, {%8,%9}, {%0,%1,%2,%3};"
                        : "+f"(acc[mi][ni][0]), "+f"(acc[mi][ni][1]),
                          "+f"(acc[mi][ni][2]), "+f"(acc[mi][ni][3])
                        : "r"(afrag[mi][0]), "r"(afrag[mi][1]), "r"(afrag[mi][2]), "r"(afrag[mi][3]),
                          "r"(bfrag[ni][0]), "r"(bfrag[ni][1]));
                }
            }
        }
    }

    // Epilogue: C (128x128 fp32) -> fp16 scatter to g_scratch [w][t][b][h]
    const int g  = lane >> 2;
    const int tg = lane & 3;
#pragma unroll
    for (int mi = 0; mi < 4; mi++) {
#pragma unroll
        for (int rr = 0; rr < 2; rr++) {
            int m = m0 + warp_m * 64 + mi * 16 + g + rr * 8;
            int bb = m >> 9;
            int t  = m & 511;
            __half* dst = g_scratch + (size_t)w_idx * TBH + (size_t)t * BH + (size_t)bb * HH
                        + nbase + warp_n * 32 + tg * 2;
#pragma unroll
            for (int ni = 0; ni < 4; ni++) {
                __half2 v = rr ? __floats2half2_rn(acc[mi][ni][2], acc[mi][ni][3])
                               : __floats2half2_rn(acc[mi][ni][0], acc[mi][ni][1]);
                *(__half2*)(dst + ni * 8) = v;
            }
        }
    }
}

// ---------------------------------------------------------------------------
// Kernel 2: diagonal recurrence scan, half2 (2 h-lanes/thread),
// depth-8 register ring prefetch.
// ---------------------------------------------------------------------------
__global__ __launch_bounds__(128)
void scan_kernel(const float* __restrict__ h0,
                 const float* __restrict__ mr,
                 const float* __restrict__ mz,
                 const float* __restrict__ br,
                 const float* __restrict__ bz,
                 float* __restrict__ out)
{
    const int idx2 = blockIdx.x * blockDim.x + threadIdx.x;   // 0..32767
    const int h2 = idx2 & 255;
    const int h  = h2 * 2;
    const int b  = idx2 >> 8;

    float2 state = *(const float2*)(h0 + (size_t)idx2 * 2);
    const float2 mrv = *(const float2*)(mr + h);
    const float2 mzv = *(const float2*)(mz + h);
    const float2 brv = *(const float2*)(br + h);
    const float2 bzv = *(const float2*)(bz + h);

    const __half2* pr = (const __half2*)g_scratch + idx2;
    const __half2* pz = (const __half2*)g_scratch + TBH2 + idx2;
    const __half2* ph = (const __half2*)g_scratch + 2u * TBH2 + idx2;

    float* o = out + (size_t)b * (TT * HH) + h;

    __half2 pa[8], pc[8], pd[8];
#pragma unroll
    for (int u = 0; u < 8; u++) {
        size_t off = (size_t)u * BH2;
        pa[u] = __ldg(pr + off);
        pc[u] = __ldg(pz + off);
        pd[u] = __ldg(ph + off);
    }

    for (int tb = 0; tb < TT; tb += 8) {
#pragma unroll
        for (int u = 0; u < 8; u++) {
            const int t = tb + u;
            float2 a0 = __half22float2(pa[u]);
            float2 c0 = __half22float2(pc[u]);
            float2 d0 = __half22float2(pd[u]);

            if (t + 8 < TT) {
                size_t off = (size_t)(t + 8) * BH2;
                pa[u] = __ldg(pr + off);
                pc[u] = __ldg(pz + off);
                pd[u] = __ldg(ph + off);
            }

            float rx = tanhf(a0.x + brv.x + state.x * mrv.x) + 1.0f;
            float ry = tanhf(a0.y + brv.y + state.y * mrv.y) + 1.0f;
            float zx = 1.0f / (1.0f + __expf(-(c0.x + bzv.x + state.x * mzv.x)));
            float zy = 1.0f / (1.0f + __expf(-(c0.y + bzv.y + state.y * mzv.y)));
            state.x = zx * state.x + (1.0f - zx) * tanhf(d0.x + rx * state.x);
            state.y = zy * state.y + (1.0f - zy) * tanhf(d0.y + ry * state.y);

            *(float2*)(o + (size_t)t * HH) = state;
        }
    }
}

// ---------------------------------------------------------------------------
// Launch
// ---------------------------------------------------------------------------
extern "C" void kernel_launch(void* const* d_in, const int* in_sizes, int n_in,
                              void* d_out, int out_size)
{
    const float* x  = (const float*)d_in[0];
    const float* h0 = (const float*)d_in[1];
    const float* wr = (const float*)d_in[2];
    const float* wz = (const float*)d_in[3];
    const float* wh = (const float*)d_in[4];
    const float* mr = (const float*)d_in[5];
    const float* mz = (const float*)d_in[6];
    const float* br = (const float*)d_in[7];
    const float* bz = (const float*)d_in[8];
    float* out = (float*)d_out;

    static int smem_set = 0;
    if (!smem_set) {
        cudaFuncSetAttribute(gemm_mma, cudaFuncAttributeMaxDynamicSharedMemorySize, GEMM_SMEM);
        smem_set = 1;
    }

    convert_x<<<(MM * DD / 4) / 256, 256>>>(x);
    convert_w<<<(3 * DD * HH) / 256, 256>>>(wr, wz, wh);

    dim3 ggrid(12, MM / 128);   // (12, 512)
    gemm_mma<<<ggrid, 256, GEMM_SMEM>>>();

    scan_kernel<<<(BH / 2) / 128, 128>>>(h0, mr, mz, br, bz, out);
}

// round 6
// speedup vs baseline: 4.0694x; 1.5583x over previous
#include <cuda_runtime.h>
#include <cuda_fp16.h>
#include <cstdint>

// Problem dims (fixed by setup_inputs)
#define BB 128
#define TT 512
#define DD 256
#define HH 512
#define BH (BB*HH)        // 65536
#define TBH (TT*BH)       // 33554432 per projection
#define MM (BB*TT)        // 65536 GEMM rows

// ---------------------------------------------------------------------------
// Static device scratch (allocation-free per harness rules)
// ---------------------------------------------------------------------------
__device__ __half g_scratch[3u * TBH];                 // 201 MB projections fp16 [w][T][B][H]
__device__ __half g_asplit[(size_t)MM * 256];          // 32 MB: [m][k] fp16
__device__ __half g_bsplit[3u * 512 * 256];            // 0.75 MB: [w][n=h][k=d] fp16

__device__ __forceinline__ uint32_t smem_u32(const void* p) {
    uint32_t a;
    asm("{ .reg .u64 t; cvta.to.shared.u64 t, %1; cvt.u32.u64 %0, t; }" : "=r"(a) : "l"(p));
    return a;
}

#define CP_ASYNC_16(smem, gmem) \
    asm volatile("cp.async.cg.shared.global [%0], [%1], 16;" :: "r"(smem), "l"(gmem))
#define CP_ASYNC_COMMIT() asm volatile("cp.async.commit_group;")
#define CP_ASYNC_WAIT_2() asm volatile("cp.async.wait_group 2;")

// ---------------------------------------------------------------------------
// Kernel 0a: x -> fp16  (A' = [M, 256])
// ---------------------------------------------------------------------------
__global__ __launch_bounds__(256)
void convert_x(const float* __restrict__ x)
{
    int i = blockIdx.x * blockDim.x + threadIdx.x;     // float4 index, total MM*256/4
    float4 v = ((const float4*)x)[i];
    union { __half b[4]; uint2 u; } H;
    H.b[0] = __float2half_rn(v.x);
    H.b[1] = __float2half_rn(v.y);
    H.b[2] = __float2half_rn(v.z);
    H.b[3] = __float2half_rn(v.w);
    *(uint2*)(g_asplit + (size_t)i * 4) = H.u;
}

// ---------------------------------------------------------------------------
// Kernel 0b: fp16 + transpose weights -> B' = [w][n=h][k=d]
// ---------------------------------------------------------------------------
__global__ __launch_bounds__(256)
void convert_w(const float* __restrict__ wr, const float* __restrict__ wz, const float* __restrict__ wh)
{
    int i = blockIdx.x * blockDim.x + threadIdx.x;     // total 3*256*512
    int w = i / (DD * HH);
    int rem = i - w * (DD * HH);
    int d = rem >> 9;
    int h = rem & 511;
    const float* W = (w == 0) ? wr : ((w == 1) ? wz : wh);
    g_bsplit[((size_t)w * 512 + h) * 256 + d] = __float2half_rn(W[d * HH + h]);
}

// ---------------------------------------------------------------------------
// Kernel 1: mma.sync fp16 GEMM, 4-stage cp.async pipeline, single pass K=256.
// Block tile 128(M) x 128(N), K-chunk 32, 8 chunks.
// 8 warps: 2 (m) x 4 (n); warp tile 64x32 via m16n8k16.f32.f16.f16.f32.
// grid = (12 n-tiles[w,nbase], 512 m-tiles), 256 threads.
// ---------------------------------------------------------------------------
#define PITCH 40
#define NSTAGE 4
#define TILE_ELT (128 * PITCH)
#define STAGE_ELT (2 * TILE_ELT)
#define GEMM_SMEM (NSTAGE * STAGE_ELT * 2)         // 81920 bytes
#define NCHUNK 8

__global__ __launch_bounds__(256, 2)
void gemm_mma()
{
    extern __shared__ __align__(16) __half sm[];

    const int tid  = threadIdx.x;
    const int wid  = tid >> 5;
    const int lane = tid & 31;
    const int warp_m = wid >> 2;       // 0..1
    const int warp_n = wid & 3;        // 0..3

    const int nt    = blockIdx.x;      // 0..11
    const int m0    = blockIdx.y * 128;
    const int w_idx = nt >> 2;
    const int nbase = (nt & 3) * 128;
    const __half* gB = g_bsplit + ((size_t)w_idx * 512 + nbase) * 256;

    float acc[4][4][4];
#pragma unroll
    for (int i = 0; i < 4; i++)
#pragma unroll
        for (int j = 0; j < 4; j++)
#pragma unroll
            for (int q = 0; q < 4; q++) acc[i][j][q] = 0.0f;

    auto load_chunk = [&](int stage, int c) {
        if (c < NCHUNK) {
            int k0 = c * 32;
            __half* As = sm + stage * STAGE_ELT;
            __half* Bs = As + TILE_ELT;
#pragma unroll
            for (int it = 0; it < 2; it++) {
                int idx = tid + it * 256;
                int r = idx >> 2, cc = (idx & 3) * 8;
                CP_ASYNC_16(smem_u32(As + r * PITCH + cc),
                            g_asplit + (size_t)(m0 + r) * 256 + k0 + cc);
                CP_ASYNC_16(smem_u32(Bs + r * PITCH + cc),
                            gB + (size_t)r * 256 + k0 + cc);
            }
        }
        CP_ASYNC_COMMIT();
    };

    load_chunk(0, 0);
    load_chunk(1, 1);
    load_chunk(2, 2);

    const int a_row_sel = warp_m * 64 + (lane & 15);
    const int a_col_sel = (lane & 16) ? 8 : 0;
    const int b_row_sel = warp_n * 32 + (lane & 7);
    const int b_col_sel = (lane & 8) ? 8 : 0;

    for (int c = 0; c < NCHUNK; c++) {
        const int st = c & (NSTAGE - 1);
        CP_ASYNC_WAIT_2();
        __syncthreads();
        load_chunk((c + 3) & (NSTAGE - 1), c + 3);

        const __half* As = sm + st * STAGE_ELT;
        const __half* Bs = As + TILE_ELT;

#pragma unroll
        for (int kk = 0; kk < 2; kk++) {
            uint32_t afrag[4][4];
            uint32_t bfrag[4][2];
#pragma unroll
            for (int mi = 0; mi < 4; mi++) {
                uint32_t addr = smem_u32(As + (a_row_sel + mi * 16) * PITCH + kk * 16 + a_col_sel);
                asm volatile("ldmatrix.sync.aligned.m8n8.x4.shared.b16 {%0,%1,%2,%3}, [%4];"
                    : "=r"(afrag[mi][0]), "=r"(afrag[mi][1]), "=r"(afrag[mi][2]), "=r"(afrag[mi][3])
                    : "r"(addr));
            }
#pragma unroll
            for (int ni = 0; ni < 4; ni++) {
                uint32_t addr = smem_u32(Bs + (b_row_sel + ni * 8) * PITCH + kk * 16 + b_col_sel);
                asm volatile("ldmatrix.sync.aligned.m8n8.x2.shared.b16 {%0,%1}, [%2];"
                    : "=r"(bfrag[ni][0]), "=r"(bfrag[ni][1])
                    : "r"(addr));
            }
#pragma unroll
            for (int mi = 0; mi < 4; mi++) {
#pragma unroll
                for (int ni = 0; ni < 4; ni++) {
                    asm volatile(
                        "mma.sync.aligned.m16n8k16.row.col.f32.f16.f16.f32 "
                        "{%0,%1,%2,%3}, {%4,%5,%6,%7}, {%8,%9}, {%0,%1,%2,%3};"
                        : "+f"(acc[mi][ni][0]), "+f"(acc[mi][ni][1]),
                          "+f"(acc[mi][ni][2]), "+f"(acc[mi][ni][3])
                        : "r"(afrag[mi][0]), "r"(afrag[mi][1]), "r"(afrag[mi][2]), "r"(afrag[mi][3]),
                          "r"(bfrag[ni][0]), "r"(bfrag[ni][1]));
                }
            }
        }
    }

    // Epilogue: C (128x128 fp32) -> fp16 scatter to g_scratch [w][t][b][h]
    const int g  = lane >> 2;
    const int tg = lane & 3;
#pragma unroll
    for (int mi = 0; mi < 4; mi++) {
#pragma unroll
        for (int rr = 0; rr < 2; rr++) {
            int m = m0 + warp_m * 64 + mi * 16 + g + rr * 8;
            int bb = m >> 9;
            int t  = m & 511;
            __half* dst = g_scratch + (size_t)w_idx * TBH + (size_t)t * BH + (size_t)bb * HH
                        + nbase + warp_n * 32 + tg * 2;
#pragma unroll
            for (int ni = 0; ni < 4; ni++) {
                __half2 v = rr ? __floats2half2_rn(acc[mi][ni][2], acc[mi][ni][3])
                               : __floats2half2_rn(acc[mi][ni][0], acc[mi][ni][1]);
                *(__half2*)(dst + ni * 8) = v;
            }
        }
    }
}

// ---------------------------------------------------------------------------
// Kernel 2: diagonal recurrence scan. 65536 threads (1 lane each),
// fp16 scratch, depth-16 register ring prefetch (48 loads in flight/thread).
// ---------------------------------------------------------------------------
#define PFD 16

__global__ __launch_bounds__(256)
void scan_kernel(const float* __restrict__ h0,
                 const float* __restrict__ mr,
                 const float* __restrict__ mz,
                 const float* __restrict__ br,
                 const float* __restrict__ bz,
                 float* __restrict__ out)
{
    const int idx = blockIdx.x * blockDim.x + threadIdx.x;   // 0..65535
    const int h = idx & (HH - 1);
    const int b = idx >> 9;

    float state = h0[idx];
    const float mrv = mr[h];
    const float mzv = mz[h];
    const float brv = br[h];
    const float bzv = bz[h];

    const __half* pr = g_scratch + idx;
    const __half* pz = g_scratch + TBH + idx;
    const __half* ph = g_scratch + 2u * TBH + idx;

    float* o = out + (size_t)b * (TT * HH) + h;

    __half pa[PFD], pc[PFD], pd[PFD];
#pragma unroll
    for (int u = 0; u < PFD; u++) {
        size_t off = (size_t)u * BH;
        pa[u] = __ldg(pr + off);
        pc[u] = __ldg(pz + off);
        pd[u] = __ldg(ph + off);
    }

    for (int tb = 0; tb < TT; tb += PFD) {
#pragma unroll
        for (int u = 0; u < PFD; u++) {
            const int t = tb + u;
            float a0 = __half2float(pa[u]);
            float c0 = __half2float(pc[u]);
            float d0 = __half2float(pd[u]);

            // Refill ring slot for t+PFD BEFORE the dependent compute chain
            if (t + PFD < TT) {
                size_t off = (size_t)(t + PFD) * BH;
                pa[u] = __ldg(pr + off);
                pc[u] = __ldg(pz + off);
                pd[u] = __ldg(ph + off);
            }

            float r = tanhf(a0 + brv + state * mrv) + 1.0f;
            float zex = __expf(-(c0 + bzv + state * mzv));
            float z = 1.0f / (1.0f + zex);
            state = z * state + (1.0f - z) * tanhf(d0 + r * state);

            o[(size_t)t * HH] = state;
        }
    }
}

// ---------------------------------------------------------------------------
// Launch
// ---------------------------------------------------------------------------
extern "C" void kernel_launch(void* const* d_in, const int* in_sizes, int n_in,
                              void* d_out, int out_size)
{
    const float* x  = (const float*)d_in[0];
    const float* h0 = (const float*)d_in[1];
    const float* wr = (const float*)d_in[2];
    const float* wz = (const float*)d_in[3];
    const float* wh = (const float*)d_in[4];
    const float* mr = (const float*)d_in[5];
    const float* mz = (const float*)d_in[6];
    const float* br = (const float*)d_in[7];
    const float* bz = (const float*)d_in[8];
    float* out = (float*)d_out;

    static int smem_set = 0;
    if (!smem_set) {
        cudaFuncSetAttribute(gemm_mma, cudaFuncAttributeMaxDynamicSharedMemorySize, GEMM_SMEM);
        smem_set = 1;
    }

    convert_x<<<(MM * DD / 4) / 256, 256>>>(x);
    convert_w<<<(3 * DD * HH) / 256, 256>>>(wr, wz, wh);

    dim3 ggrid(12, MM / 128);   // (12, 512)
    gemm_mma<<<ggrid, 256, GEMM_SMEM>>>();

    scan_kernel<<<BH / 256, 256>>>(h0, mr, mz, br, bz, out);
}

// round 7
// speedup vs baseline: 4.5819x; 1.1259x over previous
#include <cuda_runtime.h>
#include <cuda_fp16.h>
#include <cstdint>

// Problem dims (fixed by setup_inputs)
#define BB 128
#define TT 512
#define DD 256
#define HH 512
#define BH (BB*HH)        // 65536
#define TBH (TT*BH)       // 33554432 per projection
#define MM (BB*TT)        // 65536 GEMM rows

// ---------------------------------------------------------------------------
// Static device scratch (allocation-free per harness rules)
// ---------------------------------------------------------------------------
__device__ __half g_scratch[3u * TBH];                 // 201 MB projections fp16 [w][T][B][H]
__device__ __half g_asplit[(size_t)MM * 256];          // 32 MB: [m][k] fp16
__device__ __half g_bsplit[3u * 512 * 256];            // 0.75 MB: [w][n=h][k=d] fp16

__device__ __forceinline__ uint32_t smem_u32(const void* p) {
    uint32_t a;
    asm("{ .reg .u64 t; cvta.to.shared.u64 t, %1; cvt.u32.u64 %0, t; }" : "=r"(a) : "l"(p));
    return a;
}

__device__ __forceinline__ float htanh(float x) {
    float y;
    asm("tanh.approx.f32 %0, %1;" : "=f"(y) : "f"(x));
    return y;
}

#define CP_ASYNC_16(smem, gmem) \
    asm volatile("cp.async.cg.shared.global [%0], [%1], 16;" :: "r"(smem), "l"(gmem))
#define CP_ASYNC_COMMIT() asm volatile("cp.async.commit_group;")
#define CP_ASYNC_WAIT_2() asm volatile("cp.async.wait_group 2;")

// ---------------------------------------------------------------------------
// Kernel 0a: x -> fp16  (A' = [M, 256])
// ---------------------------------------------------------------------------
__global__ __launch_bounds__(256)
void convert_x(const float* __restrict__ x)
{
    int i = blockIdx.x * blockDim.x + threadIdx.x;     // float4 index, total MM*256/4
    float4 v = ((const float4*)x)[i];
    union { __half b[4]; uint2 u; } H;
    H.b[0] = __float2half_rn(v.x);
    H.b[1] = __float2half_rn(v.y);
    H.b[2] = __float2half_rn(v.z);
    H.b[3] = __float2half_rn(v.w);
    *(uint2*)(g_asplit + (size_t)i * 4) = H.u;
}

// ---------------------------------------------------------------------------
// Kernel 0b: fp16 + transpose weights -> B' = [w][n=h][k=d]
// ---------------------------------------------------------------------------
__global__ __launch_bounds__(256)
void convert_w(const float* __restrict__ wr, const float* __restrict__ wz, const float* __restrict__ wh)
{
    int i = blockIdx.x * blockDim.x + threadIdx.x;     // total 3*256*512
    int w = i / (DD * HH);
    int rem = i - w * (DD * HH);
    int d = rem >> 9;
    int h = rem & 511;
    const float* W = (w == 0) ? wr : ((w == 1) ? wz : wh);
    g_bsplit[((size_t)w * 512 + h) * 256 + d] = __float2half_rn(W[d * HH + h]);
}

// ---------------------------------------------------------------------------
// Kernel 1: mma.sync fp16 GEMM, 4-stage cp.async pipeline, single pass K=256.
// Block tile 128(M) x 128(N), K-chunk 32, 8 chunks.
// 8 warps: 2 (m) x 4 (n); warp tile 64x32 via m16n8k16.f32.f16.f16.f32.
// grid = (12 n-tiles[w,nbase], 512 m-tiles), 256 threads.
// ---------------------------------------------------------------------------
#define PITCH 40
#define NSTAGE 4
#define TILE_ELT (128 * PITCH)
#define STAGE_ELT (2 * TILE_ELT)
#define GEMM_SMEM (NSTAGE * STAGE_ELT * 2)         // 81920 bytes
#define NCHUNK 8

__global__ __launch_bounds__(256, 2)
void gemm_mma()
{
    extern __shared__ __align__(16) __half sm[];

    const int tid  = threadIdx.x;
    const int wid  = tid >> 5;
    const int lane = tid & 31;
    const int warp_m = wid >> 2;       // 0..1
    const int warp_n = wid & 3;        // 0..3

    const int nt    = blockIdx.x;      // 0..11
    const int m0    = blockIdx.y * 128;
    const int w_idx = nt >> 2;
    const int nbase = (nt & 3) * 128;
    const __half* gB = g_bsplit + ((size_t)w_idx * 512 + nbase) * 256;

    float acc[4][4][4];
#pragma unroll
    for (int i = 0; i < 4; i++)
#pragma unroll
        for (int j = 0; j < 4; j++)
#pragma unroll
            for (int q = 0; q < 4; q++) acc[i][j][q] = 0.0f;

    auto load_chunk = [&](int stage, int c) {
        if (c < NCHUNK) {
            int k0 = c * 32;
            __half* As = sm + stage * STAGE_ELT;
            __half* Bs = As + TILE_ELT;
#pragma unroll
            for (int it = 0; it < 2; it++) {
                int idx = tid + it * 256;
                int r = idx >> 2, cc = (idx & 3) * 8;
                CP_ASYNC_16(smem_u32(As + r * PITCH + cc),
                            g_asplit + (size_t)(m0 + r) * 256 + k0 + cc);
                CP_ASYNC_16(smem_u32(Bs + r * PITCH + cc),
                            gB + (size_t)r * 256 + k0 + cc);
            }
        }
        CP_ASYNC_COMMIT();
    };

    load_chunk(0, 0);
    load_chunk(1, 1);
    load_chunk(2, 2);

    const int a_row_sel = warp_m * 64 + (lane & 15);
    const int a_col_sel = (lane & 16) ? 8 : 0;
    const int b_row_sel = warp_n * 32 + (lane & 7);
    const int b_col_sel = (lane & 8) ? 8 : 0;

    for (int c = 0; c < NCHUNK; c++) {
        const int st = c & (NSTAGE - 1);
        CP_ASYNC_WAIT_2();
        __syncthreads();
        load_chunk((c + 3) & (NSTAGE - 1), c + 3);

        const __half* As = sm + st * STAGE_ELT;
        const __half* Bs = As + TILE_ELT;

#pragma unroll
        for (int kk = 0; kk < 2; kk++) {
            uint32_t afrag[4][4];
            uint32_t bfrag[4][2];
#pragma unroll
            for (int mi = 0; mi < 4; mi++) {
                uint32_t addr = smem_u32(As + (a_row_sel + mi * 16) * PITCH + kk * 16 + a_col_sel);
                asm volatile("ldmatrix.sync.aligned.m8n8.x4.shared.b16 {%0,%1,%2,%3}, [%4];"
                    : "=r"(afrag[mi][0]), "=r"(afrag[mi][1]), "=r"(afrag[mi][2]), "=r"(afrag[mi][3])
                    : "r"(addr));
            }
#pragma unroll
            for (int ni = 0; ni < 4; ni++) {
                uint32_t addr = smem_u32(Bs + (b_row_sel + ni * 8) * PITCH + kk * 16 + b_col_sel);
                asm volatile("ldmatrix.sync.aligned.m8n8.x2.shared.b16 {%0,%1}, [%2];"
                    : "=r"(bfrag[ni][0]), "=r"(bfrag[ni][1])
                    : "r"(addr));
            }
#pragma unroll
            for (int mi = 0; mi < 4; mi++) {
#pragma unroll
                for (int ni = 0; ni < 4; ni++) {
                    asm volatile(
                        "mma.sync.aligned.m16n8k16.row.col.f32.f16.f16.f32 "
                        "{%0,%1,%2,%3}, {%4,%5,%6,%7}, {%8,%9}, {%0,%1,%2,%3};"
                        : "+f"(acc[mi][ni][0]), "+f"(acc[mi][ni][1]),
                          "+f"(acc[mi][ni][2]), "+f"(acc[mi][ni][3])
                        : "r"(afrag[mi][0]), "r"(afrag[mi][1]), "r"(afrag[mi][2]), "r"(afrag[mi][3]),
                          "r"(bfrag[ni][0]), "r"(bfrag[ni][1]));
                }
            }
        }
    }

    // Epilogue: C (128x128 fp32) -> fp16 scatter to g_scratch [w][t][b][h]
    const int g  = lane >> 2;
    const int tg = lane & 3;
#pragma unroll
    for (int mi = 0; mi < 4; mi++) {
#pragma unroll
        for (int rr = 0; rr < 2; rr++) {
            int m = m0 + warp_m * 64 + mi * 16 + g + rr * 8;
            int bb = m >> 9;
            int t  = m & 511;
            __half* dst = g_scratch + (size_t)w_idx * TBH + (size_t)t * BH + (size_t)bb * HH
                        + nbase + warp_n * 32 + tg * 2;
#pragma unroll
            for (int ni = 0; ni < 4; ni++) {
                __half2 v = rr ? __floats2half2_rn(acc[mi][ni][2], acc[mi][ni][3])
                               : __floats2half2_rn(acc[mi][ni][0], acc[mi][ni][1]);
                *(__half2*)(dst + ni * 8) = v;
            }
        }
    }
}

// ---------------------------------------------------------------------------
// Kernel 2: diagonal recurrence scan. 65536 threads (1 lane each),
// fp16 scratch, depth-16 ring prefetch, HW tanh.approx on the serial chain.
//   r = tanh(pr + h*mr) + 1
//   z = sigmoid(pz + h*mz) = 0.5*tanh(0.5*arg) + 0.5
//   h' = z*h + (1-z)*tanh(ph + r*h)
// ---------------------------------------------------------------------------
#define PFD 16

__global__ __launch_bounds__(256)
void scan_kernel(const float* __restrict__ h0,
                 const float* __restrict__ mr,
                 const float* __restrict__ mz,
                 const float* __restrict__ br,
                 const float* __restrict__ bz,
                 float* __restrict__ out)
{
    const int idx = blockIdx.x * blockDim.x + threadIdx.x;   // 0..65535
    const int h = idx & (HH - 1);
    const int b = idx >> 9;

    float state = h0[idx];
    const float mrv = mr[h];
    const float mzv = mz[h];
    const float brv = br[h];
    const float bzv = bz[h];

    const __half* pr = g_scratch + idx;
    const __half* pz = g_scratch + TBH + idx;
    const __half* ph = g_scratch + 2u * TBH + idx;

    float* o = out + (size_t)b * (TT * HH) + h;

    __half pa[PFD], pc[PFD], pd[PFD];
#pragma unroll
    for (int u = 0; u < PFD; u++) {
        size_t off = (size_t)u * BH;
        pa[u] = __ldg(pr + off);
        pc[u] = __ldg(pz + off);
        pd[u] = __ldg(ph + off);
    }

    for (int tb = 0; tb < TT; tb += PFD) {
#pragma unroll
        for (int u = 0; u < PFD; u++) {
            const int t = tb + u;
            float a0 = __half2float(pa[u]);
            float c0 = __half2float(pc[u]);
            float d0 = __half2float(pd[u]);

            // Refill ring slot for t+PFD BEFORE the dependent compute chain
            if (t + PFD < TT) {
                size_t off = (size_t)(t + PFD) * BH;
                pa[u] = __ldg(pr + off);
                pc[u] = __ldg(pz + off);
                pd[u] = __ldg(ph + off);
            }

            float r = htanh(fmaf(state, mrv, a0 + brv)) + 1.0f;
            float z = fmaf(0.5f, htanh(0.5f * fmaf(state, mzv, c0 + bzv)), 0.5f);
            float inner = htanh(fmaf(r, state, d0));
            state = fmaf(z, state - inner, inner);   // z*h + (1-z)*inner

            o[(size_t)t * HH] = state;
        }
    }
}

// ---------------------------------------------------------------------------
// Launch
// ---------------------------------------------------------------------------
extern "C" void kernel_launch(void* const* d_in, const int* in_sizes, int n_in,
                              void* d_out, int out_size)
{
    const float* x  = (const float*)d_in[0];
    const float* h0 = (const float*)d_in[1];
    const float* wr = (const float*)d_in[2];
    const float* wz = (const float*)d_in[3];
    const float* wh = (const float*)d_in[4];
    const float* mr = (const float*)d_in[5];
    const float* mz = (const float*)d_in[6];
    const float* br = (const float*)d_in[7];
    const float* bz = (const float*)d_in[8];
    float* out = (float*)d_out;

    static int smem_set = 0;
    if (!smem_set) {
        cudaFuncSetAttribute(gemm_mma, cudaFuncAttributeMaxDynamicSharedMemorySize, GEMM_SMEM);
        smem_set = 1;
    }

    convert_x<<<(MM * DD / 4) / 256, 256>>>(x);
    convert_w<<<(3 * DD * HH) / 256, 256>>>(wr, wz, wh);

    dim3 ggrid(12, MM / 128);   // (12, 512)
    gemm_mma<<<ggrid, 256, GEMM_SMEM>>>();

    scan_kernel<<<BH / 256, 256>>>(h0, mr, mz, br, bz, out);
}

// round 8
// speedup vs baseline: 4.6038x; 1.0048x over previous
#include <cuda_runtime.h>
#include <cuda_fp16.h>
#include <cstdint>

// Problem dims (fixed by setup_inputs)
#define BB 128
#define TT 512
#define DD 256
#define HH 512
#define BH (BB*HH)        // 65536
#define TBH (TT*BH)       // 33554432 per projection
#define MM (BB*TT)        // 65536 GEMM rows

// ---------------------------------------------------------------------------
// Static device scratch (allocation-free per harness rules)
// ---------------------------------------------------------------------------
__device__ __half g_scratch[3u * TBH];                 // 201 MB projections fp16 [w][T][B][H]
__device__ __half g_asplit[(size_t)MM * 256];          // 32 MB: [m][k] fp16
__device__ __half g_bsplit[3u * 512 * 256];            // 0.75 MB: [w][n=h][k=d] fp16

__device__ __forceinline__ uint32_t smem_u32(const void* p) {
    uint32_t a;
    asm("{ .reg .u64 t; cvta.to.shared.u64 t, %1; cvt.u32.u64 %0, t; }" : "=r"(a) : "l"(p));
    return a;
}

__device__ __forceinline__ float htanh(float x) {
    float y;
    asm("tanh.approx.f32 %0, %1;" : "=f"(y) : "f"(x));
    return y;
}

#define CP_ASYNC_16(smem, gmem) \
    asm volatile("cp.async.cg.shared.global [%0], [%1], 16;" :: "r"(smem), "l"(gmem))
#define CP_ASYNC_COMMIT() asm volatile("cp.async.commit_group;")
#define CP_ASYNC_WAIT_2() asm volatile("cp.async.wait_group 2;")

// ---------------------------------------------------------------------------
// Kernel 0: fused converts.
//   blocks [0, XB):            x -> fp16  (A' = [M, 256])
//   blocks [XB, XB+WB):        weights -> fp16 transposed [w][n=h][k=d]
// ---------------------------------------------------------------------------
#define XB ((MM * DD / 4) / 256)          // 16384
#define WB ((3 * DD * HH) / 256)          // 1536

__global__ __launch_bounds__(256)
void convert_all(const float* __restrict__ x,
                 const float* __restrict__ wr,
                 const float* __restrict__ wz,
                 const float* __restrict__ wh)
{
    if (blockIdx.x < XB) {
        int i = blockIdx.x * 256 + threadIdx.x;        // float4 index
        float4 v = ((const float4*)x)[i];
        union { __half b[4]; uint2 u; } H;
        H.b[0] = __float2half_rn(v.x);
        H.b[1] = __float2half_rn(v.y);
        H.b[2] = __float2half_rn(v.z);
        H.b[3] = __float2half_rn(v.w);
        *(uint2*)(g_asplit + (size_t)i * 4) = H.u;
    } else {
        int i = (blockIdx.x - XB) * 256 + threadIdx.x; // total 3*256*512
        int w = i / (DD * HH);
        int rem = i - w * (DD * HH);
        int d = rem >> 9;
        int h = rem & 511;
        const float* W = (w == 0) ? wr : ((w == 1) ? wz : wh);
        g_bsplit[((size_t)w * 512 + h) * 256 + d] = __float2half_rn(W[d * HH + h]);
    }
}

// ---------------------------------------------------------------------------
// Kernel 1: mma.sync fp16 GEMM, 4-stage cp.async pipeline, single pass K=256.
// Block tile 128(M) x 128(N), K-chunk 32, 8 chunks.
// 8 warps: 2 (m) x 4 (n); warp tile 64x32 via m16n8k16.f32.f16.f16.f32.
// Bias (br for w=0, bz for w=1) folded into the epilogue.
// grid = (12 n-tiles[w,nbase], 512 m-tiles), 256 threads.
// ---------------------------------------------------------------------------
#define PITCH 40
#define NSTAGE 4
#define TILE_ELT (128 * PITCH)
#define STAGE_ELT (2 * TILE_ELT)
#define GEMM_SMEM (NSTAGE * STAGE_ELT * 2)         // 81920 bytes
#define NCHUNK 8

__global__ __launch_bounds__(256, 2)
void gemm_mma(const float* __restrict__ br, const float* __restrict__ bz)
{
    extern __shared__ __align__(16) __half sm[];

    const int tid  = threadIdx.x;
    const int wid  = tid >> 5;
    const int lane = tid & 31;
    const int warp_m = wid >> 2;       // 0..1
    const int warp_n = wid & 3;        // 0..3

    const int nt    = blockIdx.x;      // 0..11
    const int m0    = blockIdx.y * 128;
    const int w_idx = nt >> 2;
    const int nbase = (nt & 3) * 128;
    const __half* gB = g_bsplit + ((size_t)w_idx * 512 + nbase) * 256;

    float acc[4][4][4];
#pragma unroll
    for (int i = 0; i < 4; i++)
#pragma unroll
        for (int j = 0; j < 4; j++)
#pragma unroll
            for (int q = 0; q < 4; q++) acc[i][j][q] = 0.0f;

    auto load_chunk = [&](int stage, int c) {
        if (c < NCHUNK) {
            int k0 = c * 32;
            __half* As = sm + stage * STAGE_ELT;
            __half* Bs = As + TILE_ELT;
#pragma unroll
            for (int it = 0; it < 2; it++) {
                int idx = tid + it * 256;
                int r = idx >> 2, cc = (idx & 3) * 8;
                CP_ASYNC_16(smem_u32(As + r * PITCH + cc),
                            g_asplit + (size_t)(m0 + r) * 256 + k0 + cc);
                CP_ASYNC_16(smem_u32(Bs + r * PITCH + cc),
                            gB + (size_t)r * 256 + k0 + cc);
            }
        }
        CP_ASYNC_COMMIT();
    };

    load_chunk(0, 0);
    load_chunk(1, 1);
    load_chunk(2, 2);

    const int a_row_sel = warp_m * 64 + (lane & 15);
    const int a_col_sel = (lane & 16) ? 8 : 0;
    const int b_row_sel = warp_n * 32 + (lane & 7);
    const int b_col_sel = (lane & 8) ? 8 : 0;

    for (int c = 0; c < NCHUNK; c++) {
        const int st = c & (NSTAGE - 1);
        CP_ASYNC_WAIT_2();
        __syncthreads();
        load_chunk((c + 3) & (NSTAGE - 1), c + 3);

        const __half* As = sm + st * STAGE_ELT;
        const __half* Bs = As + TILE_ELT;

#pragma unroll
        for (int kk = 0; kk < 2; kk++) {
            uint32_t afrag[4][4];
            uint32_t bfrag[4][2];
            // B first (x2, cheap) so its LDSM latency hides under A's x4 loads
#pragma unroll
            for (int ni = 0; ni < 4; ni++) {
                uint32_t addr = smem_u32(Bs + (b_row_sel + ni * 8) * PITCH + kk * 16 + b_col_sel);
                asm volatile("ldmatrix.sync.aligned.m8n8.x2.shared.b16 {%0,%1}, [%2];"
                    : "=r"(bfrag[ni][0]), "=r"(bfrag[ni][1])
                    : "r"(addr));
            }
#pragma unroll
            for (int mi = 0; mi < 4; mi++) {
                uint32_t addr = smem_u32(As + (a_row_sel + mi * 16) * PITCH + kk * 16 + a_col_sel);
                asm volatile("ldmatrix.sync.aligned.m8n8.x4.shared.b16 {%0,%1,%2,%3}, [%4];"
                    : "=r"(afrag[mi][0]), "=r"(afrag[mi][1]), "=r"(afrag[mi][2]), "=r"(afrag[mi][3])
                    : "r"(addr));
            }
#pragma unroll
            for (int mi = 0; mi < 4; mi++) {
#pragma unroll
                for (int ni = 0; ni < 4; ni++) {
                    asm volatile(
                        "mma.sync.aligned.m16n8k16.row.col.f32.f16.f16.f32 "
                        "{%0,%1,%2,%3}, {%4,%5,%6,%7}, {%8,%9}, {%0,%1,%2,%3};"
                        : "+f"(acc[mi][ni][0]), "+f"(acc[mi][ni][1]),
                          "+f"(acc[mi][ni][2]), "+f"(acc[mi][ni][3])
                        : "r"(afrag[mi][0]), "r"(afrag[mi][1]), "r"(afrag[mi][2]), "r"(afrag[mi][3]),
                          "r"(bfrag[ni][0]), "r"(bfrag[ni][1]));
                }
            }
        }
    }

    // Epilogue: C (128x128 fp32) + bias -> fp16 scatter to g_scratch [w][t][b][h]
    const int g  = lane >> 2;
    const int tg = lane & 3;

    // Per-thread bias for its 8 n-columns (w=0 -> br, w=1 -> bz, w=2 -> 0)
    float2 bias[4];
    {
        const float* bsrc = (w_idx == 0) ? br : ((w_idx == 1) ? bz : nullptr);
#pragma unroll
        for (int ni = 0; ni < 4; ni++) {
            int h = nbase + warp_n * 32 + tg * 2 + ni * 8;
            bias[ni] = bsrc ? *(const float2*)(bsrc + h) : make_float2(0.f, 0.f);
        }
    }

#pragma unroll
    for (int mi = 0; mi < 4; mi++) {
#pragma unroll
        for (int rr = 0; rr < 2; rr++) {
            int m = m0 + warp_m * 64 + mi * 16 + g + rr * 8;
            int bb = m >> 9;
            int t  = m & 511;
            __half* dst = g_scratch + (size_t)w_idx * TBH + (size_t)t * BH + (size_t)bb * HH
                        + nbase + warp_n * 32 + tg * 2;
#pragma unroll
            for (int ni = 0; ni < 4; ni++) {
                float vx = (rr ? acc[mi][ni][2] : acc[mi][ni][0]) + bias[ni].x;
                float vy = (rr ? acc[mi][ni][3] : acc[mi][ni][1]) + bias[ni].y;
                *(__half2*)(dst + ni * 8) = __floats2half2_rn(vx, vy);
            }
        }
    }
}

// ---------------------------------------------------------------------------
// Kernel 2: diagonal recurrence scan. 65536 threads (1 lane each),
// fp16 scratch (biases pre-folded), depth-16 ring prefetch, HW tanh.approx.
// ---------------------------------------------------------------------------
#define PFD 16

__global__ __launch_bounds__(256)
void scan_kernel(const float* __restrict__ h0,
                 const float* __restrict__ mr,
                 const float* __restrict__ mz,
                 float* __restrict__ out)
{
    const int idx = blockIdx.x * blockDim.x + threadIdx.x;   // 0..65535
    const int h = idx & (HH - 1);
    const int b = idx >> 9;

    float state = h0[idx];
    const float mrv = mr[h];
    const float mzv = mz[h];

    const __half* pr = g_scratch + idx;
    const __half* pz = g_scratch + TBH + idx;
    const __half* ph = g_scratch + 2u * TBH + idx;

    float* o = out + (size_t)b * (TT * HH) + h;

    __half pa[PFD], pc[PFD], pd[PFD];
#pragma unroll
    for (int u = 0; u < PFD; u++) {
        size_t off = (size_t)u * BH;
        pa[u] = __ldg(pr + off);
        pc[u] = __ldg(pz + off);
        pd[u] = __ldg(ph + off);
    }

    for (int tb = 0; tb < TT; tb += PFD) {
#pragma unroll
        for (int u = 0; u < PFD; u++) {
            const int t = tb + u;
            float a0 = __half2float(pa[u]);
            float c0 = __half2float(pc[u]);
            float d0 = __half2float(pd[u]);

            // Refill ring slot for t+PFD BEFORE the dependent compute chain
            if (t + PFD < TT) {
                size_t off = (size_t)(t + PFD) * BH;
                pa[u] = __ldg(pr + off);
                pc[u] = __ldg(pz + off);
                pd[u] = __ldg(ph + off);
            }

            float r = htanh(fmaf(state, mrv, a0)) + 1.0f;
            float z = fmaf(0.5f, htanh(0.5f * fmaf(state, mzv, c0)), 0.5f);
            float inner = htanh(fmaf(r, state, d0));
            state = fmaf(z, state - inner, inner);   // z*h + (1-z)*inner

            // Streaming store: no reuse, keep L2 for scratch reads
            __stcs(o + (size_t)t * HH, state);
        }
    }
}

// ---------------------------------------------------------------------------
// Launch
// ---------------------------------------------------------------------------
extern "C" void kernel_launch(void* const* d_in, const int* in_sizes, int n_in,
                              void* d_out, int out_size)
{
    const float* x  = (const float*)d_in[0];
    const float* h0 = (const float*)d_in[1];
    const float* wr = (const float*)d_in[2];
    const float* wz = (const float*)d_in[3];
    const float* wh = (const float*)d_in[4];
    const float* mr = (const float*)d_in[5];
    const float* mz = (const float*)d_in[6];
    const float* br = (const float*)d_in[7];
    const float* bz = (const float*)d_in[8];
    float* out = (float*)d_out;

    static int smem_set = 0;
    if (!smem_set) {
        cudaFuncSetAttribute(gemm_mma, cudaFuncAttributeMaxDynamicSharedMemorySize, GEMM_SMEM);
        smem_set = 1;
    }

    convert_all<<<XB + WB, 256>>>(x, wr, wz, wh);

    dim3 ggrid(12, MM / 128);   // (12, 512)
    gemm_mma<<<ggrid, 256, GEMM_SMEM>>>(br, bz);

    scan_kernel<<<BH / 256, 256>>>(h0, mr, mz, out);
}

// round 9
// speedup vs baseline: 4.8124x; 1.0453x over previous
#include <cuda_runtime.h>
#include <cuda_fp16.h>
#include <cstdint>

// Problem dims (fixed by setup_inputs)
#define BB 128
#define TT 512
#define DD 256
#define HH 512
#define BH (BB*HH)        // 65536
#define TBH (TT*BH)       // 33554432 per projection
#define MM (BB*TT)        // 65536 GEMM rows

// ---------------------------------------------------------------------------
// Static device scratch (allocation-free per harness rules)
// ---------------------------------------------------------------------------
__device__ __half g_scratch[3u * TBH];                 // 201 MB projections fp16 [w][T][B][H]
__device__ __half g_bsplit[3u * 512 * 256];            // 0.75 MB: [w][n=h][k=d] fp16

__device__ __forceinline__ uint32_t smem_u32(const void* p) {
    uint32_t a;
    asm("{ .reg .u64 t; cvta.to.shared.u64 t, %1; cvt.u32.u64 %0, t; }" : "=r"(a) : "l"(p));
    return a;
}

__device__ __forceinline__ float htanh(float x) {
    float y;
    asm("tanh.approx.f32 %0, %1;" : "=f"(y) : "f"(x));
    return y;
}

#define CP_ASYNC_16(smem, gmem) \
    asm volatile("cp.async.cg.shared.global [%0], [%1], 16;" :: "r"(smem), "l"(gmem))
#define CP_ASYNC_COMMIT() asm volatile("cp.async.commit_group;")
#define CP_ASYNC_WAIT_2() asm volatile("cp.async.wait_group 2;")

// ---------------------------------------------------------------------------
// Kernel 0: weights -> fp16 transposed [w][n=h][k=d]  (x conversion is fused
// into the GEMM A-load now).
// ---------------------------------------------------------------------------
__global__ __launch_bounds__(256)
void convert_w(const float* __restrict__ wr,
               const float* __restrict__ wz,
               const float* __restrict__ wh)
{
    int i = blockIdx.x * 256 + threadIdx.x;        // total 3*256*512
    int w = i / (DD * HH);
    int rem = i - w * (DD * HH);
    int d = rem >> 9;
    int h = rem & 511;
    const float* W = (w == 0) ? wr : ((w == 1) ? wz : wh);
    g_bsplit[((size_t)w * 512 + h) * 256 + d] = __float2half_rn(W[d * HH + h]);
}

// ---------------------------------------------------------------------------
// Kernel 1: A-resident mma.sync fp16 GEMM.
// Each CTA: loads its 128x256 A tile ONCE (fp32 x -> fp16 smem, pitch 264),
// then computes 3 n-blocks (128 cols each) streaming B through a 4-stage ring.
// grid = (4 n-groups, 512 m-tiles), 256 threads (8 warps: 2m x 4n).
// Flat chunk loop: 24 chunks = 3 n-blocks x 8 k-chunks of 32.
// Bias (br for w=0, bz for w=1) folded into the per-n-block epilogue.
// ---------------------------------------------------------------------------
#define APITCH 264
#define BPITCH 40
#define NSTAGE 4
#define BTILE_ELT (128 * BPITCH)
#define A_BYTES (128 * APITCH * 2)                  // 67584
#define GEMM_SMEM (A_BYTES + NSTAGE * BTILE_ELT * 2) // 108544
#define NQ 24                                        // 3 n-blocks * 8 chunks

__global__ __launch_bounds__(256, 2)
void gemm_mma(const float* __restrict__ x,
              const float* __restrict__ br,
              const float* __restrict__ bz)
{
    extern __shared__ __align__(16) __half sm[];
    __half* At  = sm;                                // [128][APITCH]
    __half* Brg = sm + 128 * APITCH;                 // ring: 4 x [128][BPITCH]

    const int tid  = threadIdx.x;
    const int wid  = tid >> 5;
    const int lane = tid & 31;
    const int warp_m = wid >> 2;       // 0..1
    const int warp_n = wid & 3;        // 0..3

    const int bx = blockIdx.x;         // n-group 0..3 -> nt = bx*3 + (0..2)
    const int m0 = blockIdx.y * 128;

    float acc[4][4][4];
#pragma unroll
    for (int i = 0; i < 4; i++)
#pragma unroll
        for (int j = 0; j < 4; j++)
#pragma unroll
            for (int q = 0; q < 4; q++) acc[i][j][q] = 0.0f;

    // B chunk loader: chunk q -> n-block (q>>3), k0 = (q&7)*32
    auto load_chunk = [&](int q) {
        if (q < NQ) {
            const int nt = bx * 3 + (q >> 3);
            const int k0 = (q & 7) * 32;
            const __half* gB = g_bsplit
                + (((size_t)(nt >> 2) * 512) + (nt & 3) * 128) * 256;
            __half* Bs = Brg + (q & (NSTAGE - 1)) * BTILE_ELT;
#pragma unroll
            for (int it = 0; it < 2; it++) {
                int idx = tid + it * 256;
                int r = idx >> 2, cc = (idx & 3) * 8;
                CP_ASYNC_16(smem_u32(Bs + r * BPITCH + cc),
                            gB + (size_t)r * 256 + k0 + cc);
            }
        }
        CP_ASYNC_COMMIT();
    };

    // Prologue: kick off B ring, then load+convert A while B is in flight.
    load_chunk(0);
    load_chunk(1);
    load_chunk(2);

    // A: 128 rows x 256 fp32 -> fp16, 8192 float4, 32 per thread.
    {
        const float4* xs = (const float4*)(x + (size_t)m0 * 256);
#pragma unroll 8
        for (int it = 0; it < 32; it++) {
            int idx = tid + it * 256;
            int r = idx >> 6;
            int c4 = (idx & 63) * 4;
            float4 v = __ldg(xs + (size_t)r * 64 + (idx & 63));
            union { __half b[4]; uint2 u; } H;
            H.b[0] = __float2half_rn(v.x);
            H.b[1] = __float2half_rn(v.y);
            H.b[2] = __float2half_rn(v.z);
            H.b[3] = __float2half_rn(v.w);
            *(uint2*)(At + r * APITCH + c4) = H.u;
        }
    }

    const int a_row_sel = warp_m * 64 + (lane & 15);
    const int a_col_sel = (lane & 16) ? 8 : 0;
    const int b_row_sel = warp_n * 32 + (lane & 7);
    const int b_col_sel = (lane & 8) ? 8 : 0;

    for (int q = 0; q < NQ; q++) {
        const int st = q & (NSTAGE - 1);
        CP_ASYNC_WAIT_2();
        __syncthreads();            // B chunk q resident; A resident (first iter)
        load_chunk(q + 3);

        const int k0 = (q & 7) * 32;
        const __half* Bs = Brg + st * BTILE_ELT;

#pragma unroll
        for (int kk = 0; kk < 2; kk++) {
            uint32_t afrag[4][4];
            uint32_t bfrag[4][2];
#pragma unroll
            for (int ni = 0; ni < 4; ni++) {
                uint32_t addr = smem_u32(Bs + (b_row_sel + ni * 8) * BPITCH + kk * 16 + b_col_sel);
                asm volatile("ldmatrix.sync.aligned.m8n8.x2.shared.b16 {%0,%1}, [%2];"
                    : "=r"(bfrag[ni][0]), "=r"(bfrag[ni][1])
                    : "r"(addr));
            }
#pragma unroll
            for (int mi = 0; mi < 4; mi++) {
                uint32_t addr = smem_u32(At + (a_row_sel + mi * 16) * APITCH + k0 + kk * 16 + a_col_sel);
                asm volatile("ldmatrix.sync.aligned.m8n8.x4.shared.b16 {%0,%1,%2,%3}, [%4];"
                    : "=r"(afrag[mi][0]), "=r"(afrag[mi][1]), "=r"(afrag[mi][2]), "=r"(afrag[mi][3])
                    : "r"(addr));
            }
#pragma unroll
            for (int mi = 0; mi < 4; mi++) {
#pragma unroll
                for (int ni = 0; ni < 4; ni++) {
                    asm volatile(
                        "mma.sync.aligned.m16n8k16.row.col.f32.f16.f16.f32 "
                        "{%0,%1,%2,%3}, {%4,%5,%6,%7}, {%8,%9}, {%0,%1,%2,%3};"
                        : "+f"(acc[mi][ni][0]), "+f"(acc[mi][ni][1]),
                          "+f"(acc[mi][ni][2]), "+f"(acc[mi][ni][3])
                        : "r"(afrag[mi][0]), "r"(afrag[mi][1]), "r"(afrag[mi][2]), "r"(afrag[mi][3]),
                          "r"(bfrag[ni][0]), "r"(bfrag[ni][1]));
                }
            }
        }

        // End of an n-block: epilogue + acc reset (registers/gmem only, no smem)
        if ((q & 7) == 7) {
            const int nt    = bx * 3 + (q >> 3);
            const int w_idx = nt >> 2;
            const int nbase = (nt & 3) * 128;
            const int g  = lane >> 2;
            const int tg = lane & 3;

            const float* bsrc = (w_idx == 0) ? br : ((w_idx == 1) ? bz : nullptr);
            float2 bias[4];
#pragma unroll
            for (int ni = 0; ni < 4; ni++) {
                int hh = nbase + warp_n * 32 + tg * 2 + ni * 8;
                bias[ni] = bsrc ? *(const float2*)(bsrc + hh) : make_float2(0.f, 0.f);
            }

#pragma unroll
            for (int mi = 0; mi < 4; mi++) {
#pragma unroll
                for (int rr = 0; rr < 2; rr++) {
                    int m = m0 + warp_m * 64 + mi * 16 + g + rr * 8;
                    int bb = m >> 9;
                    int t  = m & 511;
                    __half* dst = g_scratch + (size_t)w_idx * TBH + (size_t)t * BH
                                + (size_t)bb * HH + nbase + warp_n * 32 + tg * 2;
#pragma unroll
                    for (int ni = 0; ni < 4; ni++) {
                        float vx = (rr ? acc[mi][ni][2] : acc[mi][ni][0]) + bias[ni].x;
                        float vy = (rr ? acc[mi][ni][3] : acc[mi][ni][1]) + bias[ni].y;
                        *(__half2*)(dst + ni * 8) = __floats2half2_rn(vx, vy);
                    }
                }
            }

#pragma unroll
            for (int i = 0; i < 4; i++)
#pragma unroll
                for (int j = 0; j < 4; j++)
#pragma unroll
                    for (int qq = 0; qq < 4; qq++) acc[i][j][qq] = 0.0f;
        }
    }
}

// ---------------------------------------------------------------------------
// Kernel 2: diagonal recurrence scan. 65536 threads (1 lane each),
// fp16 scratch (biases pre-folded), depth-16 ring prefetch, HW tanh.approx.
// ---------------------------------------------------------------------------
#define PFD 16

__global__ __launch_bounds__(256)
void scan_kernel(const float* __restrict__ h0,
                 const float* __restrict__ mr,
                 const float* __restrict__ mz,
                 float* __restrict__ out)
{
    const int idx = blockIdx.x * blockDim.x + threadIdx.x;   // 0..65535
    const int h = idx & (HH - 1);
    const int b = idx >> 9;

    float state = h0[idx];
    const float mrv = mr[h];
    const float mzv = mz[h];

    const __half* pr = g_scratch + idx;
    const __half* pz = g_scratch + TBH + idx;
    const __half* ph = g_scratch + 2u * TBH + idx;

    float* o = out + (size_t)b * (TT * HH) + h;

    __half pa[PFD], pc[PFD], pd[PFD];
#pragma unroll
    for (int u = 0; u < PFD; u++) {
        size_t off = (size_t)u * BH;
        pa[u] = __ldg(pr + off);
        pc[u] = __ldg(pz + off);
        pd[u] = __ldg(ph + off);
    }

    for (int tb = 0; tb < TT; tb += PFD) {
#pragma unroll
        for (int u = 0; u < PFD; u++) {
            const int t = tb + u;
            float a0 = __half2float(pa[u]);
            float c0 = __half2float(pc[u]);
            float d0 = __half2float(pd[u]);

            if (t + PFD < TT) {
                size_t off = (size_t)(t + PFD) * BH;
                pa[u] = __ldg(pr + off);
                pc[u] = __ldg(pz + off);
                pd[u] = __ldg(ph + off);
            }

            float r = htanh(fmaf(state, mrv, a0)) + 1.0f;
            float z = fmaf(0.5f, htanh(0.5f * fmaf(state, mzv, c0)), 0.5f);
            float inner = htanh(fmaf(r, state, d0));
            state = fmaf(z, state - inner, inner);   // z*h + (1-z)*inner

            __stcs(o + (size_t)t * HH, state);
        }
    }
}

// ---------------------------------------------------------------------------
// Launch
// ---------------------------------------------------------------------------
extern "C" void kernel_launch(void* const* d_in, const int* in_sizes, int n_in,
                              void* d_out, int out_size)
{
    const float* x  = (const float*)d_in[0];
    const float* h0 = (const float*)d_in[1];
    const float* wr = (const float*)d_in[2];
    const float* wz = (const float*)d_in[3];
    const float* wh = (const float*)d_in[4];
    const float* mr = (const float*)d_in[5];
    const float* mz = (const float*)d_in[6];
    const float* br = (const float*)d_in[7];
    const float* bz = (const float*)d_in[8];
    float* out = (float*)d_out;

    static int smem_set = 0;
    if (!smem_set) {
        cudaFuncSetAttribute(gemm_mma, cudaFuncAttributeMaxDynamicSharedMemorySize, GEMM_SMEM);
        smem_set = 1;
    }

    convert_w<<<(3 * DD * HH) / 256, 256>>>(wr, wz, wh);

    dim3 ggrid(4, MM / 128);   // (4, 512): 3 n-blocks per CTA
    gemm_mma<<<ggrid, 256, GEMM_SMEM>>>(x, br, bz);

    scan_kernel<<<BH / 256, 256>>>(h0, mr, mz, out);
}